// round 2
// baseline (speedup 1.0000x reference)
#include <cuda_runtime.h>

// Shapes (fixed for this problem)
//  x:      [B=4, I=64, 12,12,12,12]
//  weight: [I=64, O=64, 3,3,3,3]
//  bias:   [O=64]
//  out:    [B=4, O=64, 25,25,25,25], stride 2 transposed conv
//
// Strategy: per-block gather over output tile (b, p1, p2, p3, all o, all p4).
// Stride-2 parity: output coord p has taps k with (p-k) even, 0 <= (p-k)/2 < 12:
//   p even -> k in {0,2} (<=2 taps), p odd -> k = 1 (1 tap).
// Block loops over the <=8 (l1,l2,l3) combos; per combo stages the 48KB weight
// slice w_t[(k1,k2,k3)][k4][i][o] and the 3KB x row-slab x[b,:,l1,l2,l3,:] in
// DYNAMIC shared memory (static __shared__ is capped at 48KB and we need 51KB).

#define XB_STRIDE    1327104   // 64*12^4
#define XI_STRIDE    20736     // 12^4
#define OUT_O_STRIDE 390625    // 25^4

#define SMEM_FLOATS (3 * 64 * 64 + 64 * 12)   // 13056 floats = 52224 bytes

__device__ float w_t[81 * 64 * 64];   // [k1,k2,k3,k4][i][o]

__global__ void transpose_w_kernel(const float* __restrict__ w) {
    int idx = blockIdx.x * 256 + threadIdx.x;     // over 64*64*81, idx=(i*64+o)*81+kk
    if (idx >= 64 * 64 * 81) return;
    int kk = idx % 81;
    int io = idx / 81;
    int i = io >> 6, o = io & 63;
    w_t[kk * 4096 + i * 64 + o] = w[idx];
}

template <int TY>
__device__ __forceinline__ void compute_combo(float acc[7],
                                              const float* __restrict__ ws,
                                              const float* __restrict__ xs,
                                              int o) {
#pragma unroll 2
    for (int i = 0; i < 64; i++) {
        const float4* xr = (const float4*)(xs + i * 12);
        float4 a = xr[0], b = xr[1], c = xr[2];
        float xv[12] = {a.x, a.y, a.z, a.w, b.x, b.y, b.z, b.w, c.x, c.y, c.z, c.w};
        if ((TY & 1) == 0) {
            float w0 = ws[i * 64 + o];              // k4 = 0
            float w2 = ws[2 * 4096 + i * 64 + o];   // k4 = 2
#pragma unroll
            for (int j = 0; j < 7; j++) {
                const int p4 = TY + 4 * j;
                if (p4 <= 24) {
                    const int l0 = p4 / 2;
                    if (p4 <= 22) acc[j] = fmaf(w0, xv[l0], acc[j]);
                    if (p4 >= 2)  acc[j] = fmaf(w2, xv[l0 - 1], acc[j]);
                }
            }
        } else {
            float w1 = ws[4096 + i * 64 + o];       // k4 = 1
#pragma unroll
            for (int j = 0; j < 7; j++) {
                const int p4 = TY + 4 * j;
                if (p4 <= 24) acc[j] = fmaf(w1, xv[(p4 - 1) / 2], acc[j]);
            }
        }
    }
}

__global__ __launch_bounds__(256) void convt4d_kernel(const float* __restrict__ x,
                                                      const float* __restrict__ bias,
                                                      float* __restrict__ out) {
    extern __shared__ __align__(16) float smem[];
    float* ws_s = smem;                 // 3*64*64 floats: [k4][i][o]
    float* xs_s = smem + 3 * 64 * 64;   // 64*12 floats:   [i][l4]

    const int tid = threadIdx.x;
    const int wid = tid >> 5;
    const int lane = tid & 31;
    // Pair even-parity and odd-parity warps on the same SMSP (wid and wid+4).
    const int ty = (wid < 4) ? wid : ((wid - 4) ^ 1);
    const int o = lane + ((wid >= 4) ? 32 : 0);

    const int p3 = blockIdx.x % 25;
    const int p2 = blockIdx.x / 25;
    const int p1 = blockIdx.y;
    const int b = blockIdx.z;

    // Tap lists per spatial dim (uniform across block)
    int l1[2], k1[2], n1 = 0;
    int l2[2], k2[2], n2 = 0;
    int l3[2], k3[2], n3 = 0;
#pragma unroll
    for (int k = 0; k < 3; k++) {
        int t;
        t = p1 - k; if (t >= 0 && !(t & 1) && (t >> 1) < 12) { l1[n1] = t >> 1; k1[n1] = k; n1++; }
        t = p2 - k; if (t >= 0 && !(t & 1) && (t >> 1) < 12) { l2[n2] = t >> 1; k2[n2] = k; n2++; }
        t = p3 - k; if (t >= 0 && !(t & 1) && (t >> 1) < 12) { l3[n3] = t >> 1; k3[n3] = k; n3++; }
    }

    float acc[7];
#pragma unroll
    for (int j = 0; j < 7; j++) acc[j] = 0.0f;

    for (int c1 = 0; c1 < n1; c1++)
        for (int c2 = 0; c2 < n2; c2++)
            for (int c3 = 0; c3 < n3; c3++) {
                __syncthreads();
                // Stage weight slice (k1,k2,k3): 12288 floats, contiguous in w_t
                {
                    const float4* src =
                        (const float4*)(w_t + (k1[c1] * 27 + k2[c2] * 9 + k3[c3] * 3) * 4096);
                    float4* dst = (float4*)ws_s;
#pragma unroll
                    for (int r = 0; r < 12; r++) dst[tid + 256 * r] = src[tid + 256 * r];
                }
                // Stage x row-slab x[b, :, l1, l2, l3, 0:12]
                {
                    const float* xb =
                        x + (long)b * XB_STRIDE + l1[c1] * 1728 + l2[c2] * 144 + l3[c3] * 12;
#pragma unroll
                    for (int r = 0; r < 3; r++) {
                        int idx = tid + 256 * r;
                        int i = idx / 12, l4 = idx % 12;
                        xs_s[idx] = xb[i * XI_STRIDE + l4];
                    }
                }
                __syncthreads();
                switch (ty) {
                    case 0: compute_combo<0>(acc, ws_s, xs_s, o); break;
                    case 1: compute_combo<1>(acc, ws_s, xs_s, o); break;
                    case 2: compute_combo<2>(acc, ws_s, xs_s, o); break;
                    default: compute_combo<3>(acc, ws_s, xs_s, o); break;
                }
            }

    // Epilogue: transpose through smem so global stores are p4-contiguous.
    __syncthreads();
    float* os = ws_s;  // reuse (64 rows x 27-padded = 1728 floats)
#pragma unroll
    for (int j = 0; j < 7; j++) {
        int p4 = ty + 4 * j;
        if (p4 < 25) os[o * 27 + p4] = acc[j];
    }
    __syncthreads();

    float* ob = out + (long)b * 64 * OUT_O_STRIDE + p1 * 15625 + p2 * 625 + p3 * 25;
    for (int idx = tid; idx < 64 * 25; idx += 256) {
        int oo = idx / 25;
        int p4 = idx % 25;
        ob[(long)oo * OUT_O_STRIDE + p4] = os[oo * 27 + p4] + bias[oo];
    }
}

extern "C" void kernel_launch(void* const* d_in, const int* in_sizes, int n_in,
                              void* d_out, int out_size) {
    const float* x = (const float*)d_in[0];
    const float* w = (const float*)d_in[1];
    const float* bias = (const float*)d_in[2];
    float* out = (float*)d_out;

    static const size_t smem_bytes = SMEM_FLOATS * sizeof(float);
    cudaFuncSetAttribute(convt4d_kernel, cudaFuncAttributeMaxDynamicSharedMemorySize,
                         (int)smem_bytes);

    transpose_w_kernel<<<(64 * 64 * 81 + 255) / 256, 256>>>(w);

    dim3 grid(25 * 25, 25, 4);
    convt4d_kernel<<<grid, 256, smem_bytes>>>(x, bias, out);
}

// round 7
// speedup vs baseline: 2.0840x; 2.0840x over previous
#include <cuda_runtime.h>

// Shapes (fixed): x [4,64,12^4] f32, w [64,64,3^4], bias [64],
// out [4,64,25^4], ConvTranspose4d stride 2.
//
// Gather form with stride-2 parity: output p has taps k with (p-k) even,
// l=(p-k)/2 in [0,12). Block = (b,p1,p2,p3); loops <=8 (l1,l2,l3) combos.
// Weights read straight from L1/L2 (no smem staging). x row staged in smem
// in TWO f32x2 pair alignments so packed fma.rn.f32x2 needs no repacking:
//   xs [i][l] l=0..11 : pairs xp[j]=(x2j, x2j+1)
//   xso[i][l]         : pairs xo[j]=(x2j+1, x2j+2), x[12]:=0 pad
// Accumulators (per thread, its o, 16-channel i-slice ty):
//   aeA    = (p4=0, junk)                 += w0*xp[0]
//   ae[j]  = (p4=4j+2, p4=4j+4), j=0..5   += w0*xo[j] + w2*xp[j]
//   ao[j]  = (p4=4j+1, p4=4j+3), j=0..5   += w1*xp[j]
// 4 ty partials reduced through smem at block end.

#define XB_STRIDE    1327104   // 64*12^4
#define XI_STRIDE    20736     // 12^4
#define OUT_O_STRIDE 390625    // 25^4

typedef unsigned long long ull;

// Region A: 1856 floats (xs 768 | xso 768, later reused as out-staging 64x29)
// Region B: red[2][64][13] ull = 1664 ull
#define SMEM_BYTES (1856 * 4 + 1664 * 8)   // 7424 + 13312 = 20736 B

__device__ float w_t[81 * 64 * 64];   // [k1,k2,k3,k4][i][o]

__global__ void transpose_w_kernel(const float* __restrict__ w) {
    int idx = blockIdx.x * 256 + threadIdx.x;     // (i*64+o)*81+kk
    if (idx >= 64 * 64 * 81) return;
    int kk = idx % 81;
    int io = idx / 81;
    int i = io >> 6, o = io & 63;
    w_t[kk * 4096 + i * 64 + o] = w[idx];
}

__device__ __forceinline__ void fma2(ull& d, ull a, ull b) {
    asm("fma.rn.f32x2 %0, %1, %2, %0;" : "+l"(d) : "l"(a), "l"(b));
}
__device__ __forceinline__ void add2(ull& d, ull a) {
    asm("add.rn.f32x2 %0, %1, %0;" : "+l"(d) : "l"(a));
}
__device__ __forceinline__ ull pack2(float lo, float hi) {
    ull r; asm("mov.b64 %0, {%1, %2};" : "=l"(r) : "f"(lo), "f"(hi)); return r;
}
__device__ __forceinline__ float2 unpack2(ull v) {
    float2 r; asm("mov.b64 {%0, %1}, %2;" : "=f"(r.x), "=f"(r.y) : "l"(v)); return r;
}

__global__ __launch_bounds__(256, 4) void convt4d_kernel(const float* __restrict__ x,
                                                         const float* __restrict__ bias,
                                                         float* __restrict__ out) {
    extern __shared__ __align__(16) float smem[];
    float* xs  = smem;          // [i][l] 768 floats
    float* xso = smem + 768;    // shifted pairs, 768 floats
    float* os  = smem;          // epilogue reuse: [o][29] out staging
    ull*   red = (ull*)(smem + 1856);   // [2][64][13]

    const int tid = threadIdx.x;
    const int o   = tid & 63;
    const int ty  = tid >> 6;          // i-quarter: i in [16*ty, 16*ty+16)

    const int p3 = blockIdx.x % 25;
    const int p2 = blockIdx.x / 25;
    const int p1 = blockIdx.y;
    const int b  = blockIdx.z;

    // Tap lists (uniform across block)
    int l1[2], k1[2], n1 = 0;
    int l2[2], k2[2], n2 = 0;
    int l3[2], k3[2], n3 = 0;
#pragma unroll
    for (int k = 0; k < 3; k++) {
        int t;
        t = p1 - k; if (t >= 0 && !(t & 1) && (t >> 1) < 12) { l1[n1] = t >> 1; k1[n1] = k; n1++; }
        t = p2 - k; if (t >= 0 && !(t & 1) && (t >> 1) < 12) { l2[n2] = t >> 1; k2[n2] = k; n2++; }
        t = p3 - k; if (t >= 0 && !(t & 1) && (t >> 1) < 12) { l3[n3] = t >> 1; k3[n3] = k; n3++; }
    }

    ull acc[13];                       // [0]=aeA, [1..6]=ae, [7..12]=ao
#pragma unroll
    for (int j = 0; j < 13; j++) acc[j] = 0ULL;

    for (int c1 = 0; c1 < n1; c1++)
        for (int c2 = 0; c2 < n2; c2++)
            for (int c3 = 0; c3 < n3; c3++) {
                __syncthreads();
                // Stage x row-slab x[b,:,l1,l2,l3,0:12] in both alignments
                {
                    const float* xb = x + (long)b * XB_STRIDE
                                        + l1[c1] * 1728 + l2[c2] * 144 + l3[c3] * 12;
#pragma unroll
                    for (int r = 0; r < 3; r++) {
                        int idx = tid + 256 * r;          // < 768
                        int i = idx / 12, l = idx % 12;
                        float v = xb[i * XI_STRIDE + l];
                        xs[idx] = v;
                        if (l >= 1) xso[idx - 1] = v;
                        else        xso[idx + 11] = 0.0f;  // x[12] pad for row i
                    }
                }
                __syncthreads();

                const float* wp = w_t
                    + (k1[c1] * 27 + k2[c2] * 9 + k3[c3] * 3) * 4096   // slice (k4=0 base)
                    + ty * 16 * 64 + o;
                const float* xrow  = xs  + ty * 16 * 12;
                const float* xrowo = xso + ty * 16 * 12;

#pragma unroll 4
                for (int ii = 0; ii < 16; ii++) {
                    float w0 = wp[ii * 64];
                    float w1 = wp[4096 + ii * 64];
                    float w2 = wp[8192 + ii * 64];
                    ull ww0 = pack2(w0, w0);
                    ull ww1 = pack2(w1, w1);
                    ull ww2 = pack2(w2, w2);

                    const ulonglong2* XP = (const ulonglong2*)(xrow  + ii * 12);
                    const ulonglong2* XO = (const ulonglong2*)(xrowo + ii * 12);
                    ulonglong2 pa = XP[0], pb = XP[1], pc = XP[2];
                    ulonglong2 oa = XO[0], ob2 = XO[1], oc = XO[2];
                    ull xp[6] = {pa.x, pa.y, pb.x, pb.y, pc.x, pc.y};
                    ull xo[6] = {oa.x, oa.y, ob2.x, ob2.y, oc.x, oc.y};

                    fma2(acc[0], ww0, xp[0]);             // p4=0 (hi junk)
#pragma unroll
                    for (int j = 0; j < 6; j++) {
                        fma2(acc[1 + j], ww0, xo[j]);     // even p4: w0 taps
                        fma2(acc[1 + j], ww2, xp[j]);     // even p4: w2 taps
                        fma2(acc[7 + j], ww1, xp[j]);     // odd  p4: w1 taps
                    }
                }
            }

    // ---- reduce 4 ty partials ----
    __syncthreads();
    if (ty >= 2) {
        ull* r = red + ((ty - 2) * 64 + o) * 13;
#pragma unroll
        for (int j = 0; j < 13; j++) r[j] = acc[j];
    }
    __syncthreads();
    if (ty < 2) {
        ull* r = red + (ty * 64 + o) * 13;
#pragma unroll
        for (int j = 0; j < 13; j++) add2(acc[j], r[j]);
    }
    __syncthreads();
    if (ty == 1) {
        ull* r = red + o * 13;
#pragma unroll
        for (int j = 0; j < 13; j++) r[j] = acc[j];
    }
    __syncthreads();
    if (ty == 0) {
        ull* r = red + o * 13;
#pragma unroll
        for (int j = 0; j < 13; j++) add2(acc[j], r[j]);
        float bv = bias[o];
        float* row = os + o * 29;
        float2 t = unpack2(acc[0]);
        row[0] = t.x + bv;
#pragma unroll
        for (int j = 0; j < 6; j++) {
            t = unpack2(acc[1 + j]);
            row[4 * j + 2] = t.x + bv;
            row[4 * j + 4] = t.y + bv;
            t = unpack2(acc[7 + j]);
            row[4 * j + 1] = t.x + bv;
            row[4 * j + 3] = t.y + bv;
        }
    }
    __syncthreads();

    // Coalesced store of the 64x25 tile
    float* ob = out + (long)b * 64 * OUT_O_STRIDE + p1 * 15625 + p2 * 625 + p3 * 25;
#pragma unroll
    for (int r = 0; r < 7; r++) {
        int idx = tid + 256 * r;
        if (idx < 1600) {
            int oo = idx / 25;
            int p4 = idx % 25;
            ob[(long)oo * OUT_O_STRIDE + p4] = os[oo * 29 + p4];
        }
    }
}

extern "C" void kernel_launch(void* const* d_in, const int* in_sizes, int n_in,
                              void* d_out, int out_size) {
    const float* x = (const float*)d_in[0];
    const float* w = (const float*)d_in[1];
    const float* bias = (const float*)d_in[2];
    float* out = (float*)d_out;

    cudaFuncSetAttribute(convt4d_kernel, cudaFuncAttributeMaxDynamicSharedMemorySize,
                         SMEM_BYTES);

    transpose_w_kernel<<<(64 * 64 * 81 + 255) / 256, 256>>>(w);

    dim3 grid(25 * 25, 25, 4);
    convt4d_kernel<<<grid, 256, SMEM_BYTES>>>(x, bias, out);
}

// round 9
// speedup vs baseline: 2.6013x; 1.2482x over previous
#include <cuda_runtime.h>

// ConvTranspose4d, stride 2: x [4,64,12^4] f32, w [64,64,3^4], bias[64],
// out [4,64,25^4].
//
// Gather form with stride-2 parity (see R7). This revision: each thread owns
// TWO adjacent o outputs (o=2*lane, 2*lane+1) so one LDG.64 weight fetch and
// one set of broadcast x LDS.128 loads feed 38 fma.rn.f32x2 (vs 19 before),
// halving L1 wavefronts per MAC. 128 threads = 32 o-pairs x 4 i-quarter warps.

#define XB_STRIDE    1327104   // 64*12^4
#define XI_STRIDE    20736     // 12^4
#define OUT_O_STRIDE 390625    // 25^4

typedef unsigned long long ull;

// Region A: 1856 floats (xs 768 | xso 768 | pad; reused as out-staging 64x29)
// Region B: red 64 slots x 26 ull = 1664 ull
#define SMEM_BYTES (1856 * 4 + 1664 * 8)   // 20736 B

__device__ float w_t[81 * 64 * 64];   // [k1,k2,k3,k4][i][o]

__global__ void transpose_w_kernel(const float* __restrict__ w) {
    int idx = blockIdx.x * 256 + threadIdx.x;     // (i*64+o)*81+kk
    if (idx >= 64 * 64 * 81) return;
    int kk = idx % 81;
    int io = idx / 81;
    int i = io >> 6, o = io & 63;
    w_t[kk * 4096 + i * 64 + o] = w[idx];
}

__device__ __forceinline__ void fma2(ull& d, ull a, ull b) {
    asm("fma.rn.f32x2 %0, %1, %2, %0;" : "+l"(d) : "l"(a), "l"(b));
}
__device__ __forceinline__ void add2(ull& d, ull a) {
    asm("add.rn.f32x2 %0, %1, %0;" : "+l"(d) : "l"(a));
}
__device__ __forceinline__ ull pack2(float lo, float hi) {
    ull r; asm("mov.b64 %0, {%1, %2};" : "=l"(r) : "f"(lo), "f"(hi)); return r;
}
__device__ __forceinline__ float2 unpack2(ull v) {
    float2 r; asm("mov.b64 {%0, %1}, %2;" : "=f"(r.x), "=f"(r.y) : "l"(v)); return r;
}

__global__ __launch_bounds__(128) void convt4d_kernel(const float* __restrict__ x,
                                                      const float* __restrict__ bias,
                                                      float* __restrict__ out) {
    extern __shared__ __align__(16) float smem[];
    float* xs  = smem;          // [i][l] 768 floats
    float* xso = smem + 768;    // shifted pairs (x[i][l+1], pad 0), 768 floats
    float* os  = smem;          // epilogue reuse: [o][29] out staging
    ull*   red = (ull*)(smem + 1856);   // 64 slots x 26 ull

    const int tid  = threadIdx.x;
    const int lane = tid & 31;         // o-pair index: o = 2*lane, 2*lane+1
    const int ty   = tid >> 5;         // i-quarter: i in [16*ty, 16*ty+16)

    const int p3 = blockIdx.x % 25;
    const int p2 = blockIdx.x / 25;
    const int p1 = blockIdx.y;
    const int b  = blockIdx.z;

    // Tap lists (uniform across block)
    int l1[2], k1[2], n1 = 0;
    int l2[2], k2[2], n2 = 0;
    int l3[2], k3[2], n3 = 0;
#pragma unroll
    for (int k = 0; k < 3; k++) {
        int t;
        t = p1 - k; if (t >= 0 && !(t & 1) && (t >> 1) < 12) { l1[n1] = t >> 1; k1[n1] = k; n1++; }
        t = p2 - k; if (t >= 0 && !(t & 1) && (t >> 1) < 12) { l2[n2] = t >> 1; k2[n2] = k; n2++; }
        t = p3 - k; if (t >= 0 && !(t & 1) && (t >> 1) < 12) { l3[n3] = t >> 1; k3[n3] = k; n3++; }
    }

    // acc layout per o: [0]=p4 0 (hi junk), [1..6]=(4j+2,4j+4), [7..12]=(4j+1,4j+3)
    ull accA[13], accB[13];
#pragma unroll
    for (int j = 0; j < 13; j++) { accA[j] = 0ULL; accB[j] = 0ULL; }

    for (int c1 = 0; c1 < n1; c1++)
        for (int c2 = 0; c2 < n2; c2++)
            for (int c3 = 0; c3 < n3; c3++) {
                __syncthreads();
                // Stage x row-slab x[b,:,l1,l2,l3,0:12] in both pair alignments
                {
                    const float* xb = x + (long)b * XB_STRIDE
                                        + l1[c1] * 1728 + l2[c2] * 144 + l3[c3] * 12;
#pragma unroll
                    for (int r = 0; r < 6; r++) {
                        int idx = tid + 128 * r;          // < 768
                        int i = idx / 12, l = idx % 12;
                        float v = xb[i * XI_STRIDE + l];
                        xs[idx] = v;
                        if (l >= 1) xso[idx - 1] = v;
                        else        xso[idx + 11] = 0.0f;  // x[12] pad for row i
                    }
                }
                __syncthreads();

                const float* wp = w_t
                    + (k1[c1] * 27 + k2[c2] * 9 + k3[c3] * 3) * 4096   // slice base (k4=0)
                    + ty * 1024 + 2 * lane;
                const float* xrow  = xs  + ty * 192;
                const float* xrowo = xso + ty * 192;

#pragma unroll 4
                for (int ii = 0; ii < 16; ii++) {
                    float2 w0 = *(const float2*)(wp + ii * 64);           // k4=0: o, o+1
                    float2 w1 = *(const float2*)(wp + 4096 + ii * 64);    // k4=1
                    float2 w2 = *(const float2*)(wp + 8192 + ii * 64);    // k4=2
                    ull w0a = pack2(w0.x, w0.x), w0b = pack2(w0.y, w0.y);
                    ull w1a = pack2(w1.x, w1.x), w1b = pack2(w1.y, w1.y);
                    ull w2a = pack2(w2.x, w2.x), w2b = pack2(w2.y, w2.y);

                    const ulonglong2* XP = (const ulonglong2*)(xrow  + ii * 12);
                    const ulonglong2* XO = (const ulonglong2*)(xrowo + ii * 12);
                    ulonglong2 pa = XP[0], pb = XP[1], pc = XP[2];
                    ulonglong2 oa = XO[0], ob2 = XO[1], oc = XO[2];
                    ull xp[6] = {pa.x, pa.y, pb.x, pb.y, pc.x, pc.y};
                    ull xo[6] = {oa.x, oa.y, ob2.x, ob2.y, oc.x, oc.y};

                    fma2(accA[0], w0a, xp[0]);             // p4=0 (hi junk)
                    fma2(accB[0], w0b, xp[0]);
#pragma unroll
                    for (int j = 0; j < 6; j++) {
                        fma2(accA[1 + j], w0a, xo[j]);     // even p4: w0 taps
                        fma2(accA[1 + j], w2a, xp[j]);     // even p4: w2 taps
                        fma2(accA[7 + j], w1a, xp[j]);     // odd  p4: w1 taps
                        fma2(accB[1 + j], w0b, xo[j]);
                        fma2(accB[1 + j], w2b, xp[j]);
                        fma2(accB[7 + j], w1b, xp[j]);
                    }
                }
            }

    // ---- reduce 4 ty partials (per o-pair slot) ----
    __syncthreads();
    if (ty >= 2) {
        ull* r = red + ((ty - 2) * 32 + lane) * 26;
#pragma unroll
        for (int j = 0; j < 13; j++) { r[j] = accA[j]; r[13 + j] = accB[j]; }
    }
    __syncthreads();
    if (ty < 2) {
        ull* r = red + (ty * 32 + lane) * 26;
#pragma unroll
        for (int j = 0; j < 13; j++) { add2(accA[j], r[j]); add2(accB[j], r[13 + j]); }
    }
    __syncthreads();
    if (ty == 1) {
        ull* r = red + lane * 26;
#pragma unroll
        for (int j = 0; j < 13; j++) { r[j] = accA[j]; r[13 + j] = accB[j]; }
    }
    __syncthreads();
    if (ty == 0) {
        ull* r = red + lane * 26;
#pragma unroll
        for (int j = 0; j < 13; j++) { add2(accA[j], r[j]); add2(accB[j], r[13 + j]); }
        const int oa_ = 2 * lane, ob_ = 2 * lane + 1;
        float bva = bias[oa_], bvb = bias[ob_];
        float* rowA = os + oa_ * 29;
        float* rowB = os + ob_ * 29;
        float2 t;
        t = unpack2(accA[0]); rowA[0] = t.x + bva;
        t = unpack2(accB[0]); rowB[0] = t.x + bvb;
#pragma unroll
        for (int j = 0; j < 6; j++) {
            t = unpack2(accA[1 + j]); rowA[4 * j + 2] = t.x + bva; rowA[4 * j + 4] = t.y + bva;
            t = unpack2(accA[7 + j]); rowA[4 * j + 1] = t.x + bva; rowA[4 * j + 3] = t.y + bva;
            t = unpack2(accB[1 + j]); rowB[4 * j + 2] = t.x + bvb; rowB[4 * j + 4] = t.y + bvb;
            t = unpack2(accB[7 + j]); rowB[4 * j + 1] = t.x + bvb; rowB[4 * j + 3] = t.y + bvb;
        }
    }
    __syncthreads();

    // Coalesced store of the 64x25 tile
    float* ob = out + (long)b * 64 * OUT_O_STRIDE + p1 * 15625 + p2 * 625 + p3 * 25;
    for (int idx = tid; idx < 1600; idx += 128) {
        int oo = idx / 25;
        int p4 = idx % 25;
        ob[(long)oo * OUT_O_STRIDE + p4] = os[oo * 29 + p4];
    }
}

extern "C" void kernel_launch(void* const* d_in, const int* in_sizes, int n_in,
                              void* d_out, int out_size) {
    const float* x = (const float*)d_in[0];
    const float* w = (const float*)d_in[1];
    const float* bias = (const float*)d_in[2];
    float* out = (float*)d_out;

    cudaFuncSetAttribute(convt4d_kernel, cudaFuncAttributeMaxDynamicSharedMemorySize,
                         SMEM_BYTES);

    transpose_w_kernel<<<(64 * 64 * 81 + 255) / 256, 256>>>(w);

    dim3 grid(25 * 25, 25, 4);
    convt4d_kernel<<<grid, 128, SMEM_BYTES>>>(x, bias, out);
}